// round 15
// baseline (speedup 1.0000x reference)
#include <cuda_runtime.h>

// Problem shape (fixed by setup_inputs): x: (B=4, S=4096, D=64) f32; out: (B,S) f32
#define S_LEN  4096
#define D_DIM  64
#define CH     8               // chunk size (norm elements per chunk min)
#define NCH    (S_LEN / CH)    // 512 chunks per row
#define NB     128             // grid (co-resident: 128 <= 148 SMs)
#define NT     512             // threads per block
#define QPB    128             // queries/rows per block (32 segments per batch row)
#define NSTG   11              // staging warps (warps 1..11)

// Device-global scratch (no allocation). Flags are MONOTONIC across graph
// replays (one producer per flag, +1 per launch; at entry of a replay every
// flag equals the replay count, so target = own-flag-at-entry + 1).
__device__ float    g_norms[4 * S_LEN];     // per-(b,t) L1 norms
__device__ float    g_L1[4 * NCH];          // per-(b,chunk) 8-row minima
__device__ float    g_L16[4 * 32];          // per-(b,segment) 128-row minima
__device__ unsigned g_flag[4][32];          // flag[b][s]: segment s of batch b done

__device__ __forceinline__ unsigned ld_acquire_gpu(const unsigned* p) {
    unsigned v;
    asm volatile("ld.acquire.gpu.global.u32 %0, [%1];" : "=r"(v) : "l"(p) : "memory");
    return v;
}
__device__ __forceinline__ unsigned ld_relaxed_gpu(const unsigned* p) {
    unsigned v;
    asm volatile("ld.relaxed.gpu.global.u32 %0, [%1];" : "=r"(v) : "l"(p) : "memory");
    return v;
}
__device__ __forceinline__ void red_release_add(unsigned* p, unsigned v) {
    asm volatile("red.release.gpu.global.add.u32 [%0], %1;" :: "l"(p), "r"(v) : "memory");
}

__device__ __forceinline__ float abs4(float4 v) {
    return fabsf(v.x) + fabsf(v.y) + fabsf(v.z) + fabsf(v.w);
}

// Largest k in [0, count) with tab[base+k] < thr, else -1.
// N independent predicated loads, then a balanced tree max (short dep chain).
template <int N>
__device__ __forceinline__ int last_hit(const float* __restrict__ tab,
                                        int base, int count, float thr) {
    int v[N];
#pragma unroll
    for (int k = 0; k < N; k++) {
        const bool in = k < count;
        const float val = tab[base + (in ? k : 0)];   // clamped, always safe
        v[k] = (in && val < thr) ? k : -1;
    }
#pragma unroll
    for (int s = N / 2; s > 0; s >>= 1)
#pragma unroll
        for (int k = 0; k < s; k++) v[k] = max(v[k], v[k + s]);
    return v[0];
}

__global__ void __launch_bounds__(NT, 1) fused_kernel(const float* __restrict__ x,
                                                      float* __restrict__ out) {
    __shared__ float sn[S_LEN];      // norms: own segment (phase1) + staged prefix
    __shared__ float sL1[NCH];       // chunk minima: own (phase1) + staged prefix
    __shared__ float ssg[32];        // segment minima (staged prefix)

    const int tid  = threadIdx.x;
    const int lane = tid & 31;
    const int warp = tid >> 5;         // 16 warps = 16 chunks of own segment
    const int seg  = blockIdx.x >> 2;  // 0..31 (low segments dispatch first)
    const int b    = blockIdx.x & 3;   // batch row

    // Per-replay target (per warp): own flag is only touched by this block,
    // and this read precedes bar1 (hence precedes our own release).
    unsigned tgt = 0;
    if (lane == 0) tgt = ld_relaxed_gpu(&g_flag[b][seg]) + 1u;
    tgt = __shfl_sync(0xffffffffu, tgt, 0);

    // ---------- Phase 1: norms + chunk minima for segment (b, seg) ----------
    // 4 threads per row, 4 back-to-back float4 loads (MLP=4, coalesced 2KB/warp).
    // Each warp covers exactly 8 rows = one chunk -> warp shfl-min = chunk min.
    {
        const int rloc = tid >> 2;               // 0..127
        const int q    = tid & 3;
        const int row  = b * S_LEN + seg * QPB + rloc;
        const float4* src = reinterpret_cast<const float4*>(x + (size_t)row * D_DIM) + q * 4;
        const float4 a0 = src[0];
        const float4 a1 = src[1];
        const float4 a2 = src[2];
        const float4 a3 = src[3];
        float s = (abs4(a0) + abs4(a1)) + (abs4(a2) + abs4(a3));
        s += __shfl_xor_sync(0xffffffffu, s, 1);
        s += __shfl_xor_sync(0xffffffffu, s, 2);   // row sum in all 4 row-lanes
        if (q == 0) {
            g_norms[row] = s;
            sn[seg * QPB + rloc] = s;              // own norms live in smem
        }
        float m = s;                               // min over the warp's 8 rows
#pragma unroll
        for (int o = 16; o > 0; o >>= 1)
            m = fminf(m, __shfl_xor_sync(0xffffffffu, m, o));
        if (lane == 0) {
            const int cglob = seg * 16 + warp;
            g_L1[b * NCH + cglob] = m;
            sL1[cglob] = m;                        // own chunk minima in smem
        }
    }
    __syncthreads();   // bar1: own norms/chunk-minima visible block-wide

    // ---------- Concurrent roles after bar1 ----------
    // warp 0      : segment min (parallel shfl tree) -> publish -> release
    // warps 1..11 : stage prefix segments as their flags flip (pipelined)
    // warps 12..15: phase A + B1 queries on own-segment smem (overlap window)
    if (warp == 0) {
        float m = sL1[seg * 16 + (lane & 15)];     // duplicated halves, same min
#pragma unroll
        for (int o = 8; o > 0; o >>= 1)
            m = fminf(m, __shfl_xor_sync(0xffffffffu, m, o));
        if (lane == 0) {
            g_L16[b * 32 + seg] = m;
            red_release_add(&g_flag[b][seg], 1u);  // publish segment
        }
    } else if (warp <= NSTG) {
        // Stage segments s = warp-1, warp-1+11, ... (< seg), in flag order.
        for (int s = warp - 1; s < seg; s += NSTG) {
            if (lane == 0)
                while (ld_acquire_gpu(&g_flag[b][s]) < tgt) { }
            __syncwarp();                          // order loads after acquire
            // 128 norms = 32 float4 (1/lane) + 16 chunk minima + 1 segment min.
            const float4 v = reinterpret_cast<const float4*>(
                g_norms + (size_t)b * S_LEN + s * QPB)[lane];
            reinterpret_cast<float4*>(sn + s * QPB)[lane] = v;
            if (lane < 16)      sL1[s * 16 + lane] = g_L1[b * NCH + s * 16 + lane];
            else if (lane == 16) ssg[s] = g_L16[b * 32 + s];
        }
    }

    int   t = 0, best = -1;
    float thr = 0.0f;
    if (tid >= 384) {
        const int qid = tid - 384;
        t   = seg * QPB + qid;
        thr = 0.7f * (sn[t] + 1e-8f);
        // A) partial chunk [t&~7, t) — own segment smem.
        const int cb = t & ~(CH - 1);
        const int ka = last_hit<CH>(sn, cb, t - cb, thr);
        if (ka >= 0) best = cb + ka;
        // B1) full own-segment chunks below chunk(t).
        if (best < 0) {
            const int nown = (t >> 3) - seg * 16;          // 0..15
            const int kb = last_hit<16>(sL1, seg * 16, nown, thr);
            if (kb >= 0) {
                const int base = (seg * 16 + kb) * CH;     // dirty chunk (own smem)
                best = base + last_hit<CH>(sn, base, CH, thr);
            }
        }
        if (best >= 0)   // prefix-independent result: store immediately
            out[(size_t)b * S_LEN + t] = (float)(t - best);
    }
    __syncthreads();   // bar2: all staged prefix data visible

    // ---------- Resolve remaining queries: B2 -> B3 -> C (all smem) ---------
    if (tid >= 384 && best < 0) {
        int j = -1;
        if (seg > 0) {
            const int s = last_hit<32>(ssg, 0, seg, thr);         // dirty segment
            if (s >= 0) {
                const int c = last_hit<16>(sL1, s * 16, 16, thr); // dirty chunk (guaranteed)
                const int base = (s * 16 + c) * CH;
                j = base + last_hit<CH>(sn, base, CH, thr);       // dirty elem (guaranteed)
            }
        }
        out[(size_t)b * S_LEN + t] = j >= 0 ? (float)(t - j) : 0.0f;
    }
}

// ---------------------------------------------------------------------------
// Launch: single fused kernel, 128 blocks x 512 threads.
// ---------------------------------------------------------------------------
extern "C" void kernel_launch(void* const* d_in, const int* in_sizes, int n_in,
                              void* d_out, int out_size) {
    const float* x = (const float*)d_in[0];
    float* out = (float*)d_out;
    fused_kernel<<<NB, NT>>>(x, out);
}

// round 16
// speedup vs baseline: 1.1513x; 1.1513x over previous
#include <cuda_runtime.h>

// Problem shape (fixed by setup_inputs): x: (B=4, S=4096, D=64) f32; out: (B,S) f32
#define S_LEN  4096
#define D_DIM  64
#define CH     8               // chunk size (norm elements per chunk min)
#define NCH    (S_LEN / CH)    // 512 chunks per row
#define NB     128             // grid (co-resident: 128 <= 148 SMs)
#define NT     512             // threads per block
#define QPB    128             // queries/rows per block (32 segments per batch row)

// Device-global scratch (no allocation). Flags are MONOTONIC across graph
// replays (one producer per flag, +1 per launch; per-replay target derived
// from the producer's own flag value at entry).
__device__ float    g_norms[4 * S_LEN];     // per-(b,t) L1 norms
__device__ float    g_L1[4 * NCH];          // per-(b,chunk) 8-row minima
__device__ float    g_L16[4 * 32];          // per-(b,segment) 128-row minima
__device__ unsigned g_flag[4][32];          // flag[b][s]: segment s of batch b done

__device__ __forceinline__ unsigned ld_acquire_gpu(const unsigned* p) {
    unsigned v;
    asm volatile("ld.acquire.gpu.global.u32 %0, [%1];" : "=r"(v) : "l"(p) : "memory");
    return v;
}
__device__ __forceinline__ unsigned ld_relaxed_gpu(const unsigned* p) {
    unsigned v;
    asm volatile("ld.relaxed.gpu.global.u32 %0, [%1];" : "=r"(v) : "l"(p) : "memory");
    return v;
}
__device__ __forceinline__ void red_release_add(unsigned* p, unsigned v) {
    asm volatile("red.release.gpu.global.add.u32 [%0], %1;" :: "l"(p), "r"(v) : "memory");
}

__device__ __forceinline__ float abs4(float4 v) {
    return fabsf(v.x) + fabsf(v.y) + fabsf(v.z) + fabsf(v.w);
}

// Largest k in [0, count) with tab[base+k] < thr, else -1.
// N independent predicated loads, then a balanced tree max (short dep chain).
template <int N>
__device__ __forceinline__ int last_hit(const float* __restrict__ tab,
                                        int base, int count, float thr) {
    int v[N];
#pragma unroll
    for (int k = 0; k < N; k++) {
        const bool in = k < count;
        const float val = tab[base + (in ? k : 0)];   // clamped, always safe
        v[k] = (in && val < thr) ? k : -1;
    }
#pragma unroll
    for (int s = N / 2; s > 0; s >>= 1)
#pragma unroll
        for (int k = 0; k < s; k++) v[k] = max(v[k], v[k + s]);
    return v[0];
}

__global__ void __launch_bounds__(NT, 1) fused_kernel(const float* __restrict__ x,
                                                      float* __restrict__ out) {
    __shared__ float sn[S_LEN];      // norms: own segment (phase1) + staged prefix
    __shared__ float sL1[NCH];       // chunk minima: own (phase1) + staged prefix
    __shared__ float ssg[32];        // segment minima (staged prefix)

    const int tid  = threadIdx.x;
    const int lane = tid & 31;
    const int warp = tid >> 5;         // 16 warps = 16 chunks of own segment
    const int seg  = blockIdx.x >> 2;  // 0..31 (low segments dispatch first)
    const int b    = blockIdx.x & 3;   // batch row

    // Per-replay target: only THIS block increments flag[b][seg].
    unsigned target = 0;
    if (tid == 0) target = ld_relaxed_gpu(&g_flag[b][seg]) + 1u;

    // ---------- Phase 1: norms + chunk minima for segment (b, seg) ----------
    // 4 threads per row, 4 back-to-back float4 loads (MLP=4, coalesced 2KB/warp).
    // Each warp covers exactly 8 rows = one chunk -> warp shfl-min = chunk min.
    {
        const int rloc = tid >> 2;               // 0..127
        const int q    = tid & 3;
        const int row  = b * S_LEN + seg * QPB + rloc;
        const float4* src = reinterpret_cast<const float4*>(x + (size_t)row * D_DIM) + q * 4;
        const float4 a0 = src[0];
        const float4 a1 = src[1];
        const float4 a2 = src[2];
        const float4 a3 = src[3];
        float s = (abs4(a0) + abs4(a1)) + (abs4(a2) + abs4(a3));
        s += __shfl_xor_sync(0xffffffffu, s, 1);
        s += __shfl_xor_sync(0xffffffffu, s, 2);   // row sum in all 4 row-lanes
        if (q == 0) {
            g_norms[row] = s;
            sn[seg * QPB + rloc] = s;              // own norms live in smem
        }
        float m = s;                               // min over the warp's 8 rows
#pragma unroll
        for (int o = 16; o > 0; o >>= 1)
            m = fminf(m, __shfl_xor_sync(0xffffffffu, m, o));
        if (lane == 0) {
            const int cglob = seg * 16 + warp;
            g_L1[b * NCH + cglob] = m;
            sL1[cglob] = m;                        // own chunk minima in smem
        }
    }
    __syncthreads();   // bar1: own norms/chunk-minima visible block-wide

    // tid 0: segment min (16 chunk minima) -> publish, then release.
    if (tid == 0) {
        float m = sL1[seg * 16];
#pragma unroll
        for (int k = 1; k < 16; k++) m = fminf(m, sL1[seg * 16 + k]);
        g_L16[b * 32 + seg] = m;
        red_release_add(&g_flag[b][seg], 1u);      // publish segment
    }

    // ---------- Overlap window: poll (warp 0) || phase A+B1 (warps 12-15) ---
    // Queries: tid 384..511, qid = tid-384, t = seg*128 + qid.
    int   t = 0, best = -1;
    float thr = 0.0f;
    if (tid >= 384) {
        const int qid = tid - 384;
        t   = seg * QPB + qid;
        thr = 0.7f * (sn[t] + 1e-8f);
        // A) partial chunk [t&~7, t) — own segment smem.
        const int cb = t & ~(CH - 1);
        const int ka = last_hit<CH>(sn, cb, t - cb, thr);
        if (ka >= 0) best = cb + ka;
        // B1) full own-segment chunks below chunk(t).
        if (best < 0) {
            const int nown = (t >> 3) - seg * 16;          // 0..15
            const int kb = last_hit<16>(sL1, seg * 16, nown, thr);
            if (kb >= 0) {
                const int base = (seg * 16 + kb) * CH;     // dirty chunk (own smem)
                best = base + last_hit<CH>(sn, base, CH, thr);
            }
        }
        if (best >= 0)   // prefix-independent result: store immediately
            out[(size_t)b * S_LEN + t] = (float)(t - best);
    }
    if (tid < 32 && seg > 0) {   // read-only acquire poll on flags 0..seg-1
        const unsigned tgt = __shfl_sync(0xffffffffu, target, 0);
        bool done = lane >= seg;
        while (!__all_sync(0xffffffffu, done)) {
            if (!done) done = ld_acquire_gpu(&g_flag[b][lane]) >= tgt;
        }
    }
    __syncthreads();   // bar2: prefix globals now visible

    // ---------- Stage prefix (ONE parallel L2 round), no table builds -------
    if (tid < seg * 16) {       // prefix norms (2 LDG) + prefix chunk minima (1 LDG)
        const float4* p = reinterpret_cast<const float4*>(g_norms + (size_t)b * S_LEN) + 2 * tid;
        const float4 a0 = p[0];
        const float4 a1 = p[1];
        float4* dst = reinterpret_cast<float4*>(sn);
        dst[2 * tid + 0] = a0;
        dst[2 * tid + 1] = a1;
        sL1[tid] = g_L1[b * NCH + tid];
    }
    if (tid >= 480 && tid - 480 < seg)    // segment minima (lanes of warp 15)
        ssg[tid - 480] = g_L16[b * 32 + (tid - 480)];
    __syncthreads();   // bar3: staged prefix visible

    // ---------- Resolve remaining queries: B2 -> B3 -> C (all smem) ---------
    if (tid >= 384 && best < 0) {
        int j = -1;
        if (seg > 0) {
            const int s = last_hit<32>(ssg, 0, seg, thr);         // dirty segment
            if (s >= 0) {
                const int c = last_hit<16>(sL1, s * 16, 16, thr); // dirty chunk (guaranteed)
                const int base = (s * 16 + c) * CH;
                j = base + last_hit<CH>(sn, base, CH, thr);       // dirty elem (guaranteed)
            }
        }
        out[(size_t)b * S_LEN + t] = j >= 0 ? (float)(t - j) : 0.0f;
    }
}

// ---------------------------------------------------------------------------
// Launch: single fused kernel, 128 blocks x 512 threads.
// ---------------------------------------------------------------------------
extern "C" void kernel_launch(void* const* d_in, const int* in_sizes, int n_in,
                              void* d_out, int out_size) {
    const float* x = (const float*)d_in[0];
    float* out = (float*)d_out;
    fused_kernel<<<NB, NT>>>(x, out);
}